// round 16
// baseline (speedup 1.0000x reference)
#include <cuda_runtime.h>

#define NB 32
#define HIDDEN 256
#define NQH 4
#define NKVH 2
#define HD 64
#define QKV_DIM 512
#define MAXS 8192
#define CHUNK 256
#define NCHUNK (MAXS / CHUNK)          // 32 == warp size (outproj phase-1 relies on this)
#define NHEAD (NB * NQH)               // 128
#define DV (NKVH * MAXS * (HD / 4))    // float4 offset k-plane -> v-plane

// ---------------- scratch (device globals) ----------------------------------
__device__ float g_q[NB * HIDDEN];
__device__ float g_k[NB * NKVH * HD];
__device__ float g_v[NB * NKVH * HD];
__device__ float g_pm[NHEAD * NCHUNK];
__device__ float g_pl[NHEAD * NCHUNK];
__device__ float g_pa[NHEAD * NCHUNK * HD];

__device__ __forceinline__ float dot4(float4 a, float4 b) {
    return a.x * b.x + a.y * b.y + a.z * b.z + a.w * b.w;
}

// ---------------- kernel 1: qkv projection + rope, warp-per-rope-pair -------
// (R7/R9 exact: 8192 warps, chain depth 1, measured ~6.2us)
__global__ void __launch_bounds__(256) qkv_rope_kernel(
    const float* __restrict__ x, const int* __restrict__ ctx_len,
    const float* __restrict__ rope, const float* __restrict__ qkv_w,
    const float* __restrict__ qkv_b)
{
    int W    = blockIdx.x * 8 + (threadIdx.x >> 5);
    int lane = threadIdx.x & 31;
    int b    = W & 31;
    int d    = (W >> 5) & 31;
    int hid  = W >> 10;                   // 0..7
    int elo  = hid * HD + d;
    int ehi  = elo + 32;

    const float4* wlo = (const float4*)(qkv_w + (size_t)elo * HIDDEN) + lane * 2;
    const float4* whi = (const float4*)(qkv_w + (size_t)ehi * HIDDEN) + lane * 2;
    const float4* xb  = (const float4*)(x + (size_t)b * HIDDEN) + lane * 2;

    float4 wl0 = wlo[0], wl1 = wlo[1];
    float4 wh0 = whi[0], wh1 = whi[1];
    float4 x0  = xb[0],  x1  = xb[1];

    float slo = dot4(wl0, x0) + dot4(wl1, x1);
    float shi = dot4(wh0, x0) + dot4(wh1, x1);
#pragma unroll
    for (int s = 16; s > 0; s >>= 1) {
        slo += __shfl_xor_sync(0xffffffffu, slo, s);
        shi += __shfl_xor_sync(0xffffffffu, shi, s);
    }

    if (lane == 0) {
        slo += qkv_b[elo];
        shi += qkv_b[ehi];
        float vlo, vhi;
        if (hid < NQH + NKVH) {           // q or k: rope
            int pos = ctx_len[b];
            float c = rope[(size_t)pos * HD + d];
            float s = rope[(size_t)pos * HD + 32 + d];
            vlo = slo * c - shi * s;
            vhi = slo * s + shi * c;
        } else {
            vlo = slo; vhi = shi;
        }
        if (hid < NQH) {
            g_q[b * HIDDEN + hid * HD + d]      = vlo;
            g_q[b * HIDDEN + hid * HD + d + 32] = vhi;
        } else if (hid < NQH + NKVH) {
            int hk = hid - NQH;
            g_k[(b * NKVH + hk) * HD + d]      = vlo;
            g_k[(b * NKVH + hk) * HD + d + 32] = vhi;
        } else {
            int hv = hid - NQH - NKVH;
            g_v[(b * NKVH + hv) * HD + d]      = vlo;
            g_v[(b * NKVH + hv) * HD + d + 32] = vhi;
        }
    }
}

// ---------------- kernel 2: fused KV-cache copy + flash-decode partials -----
// 2048 CTAs x 256 threads; 5 CTAs/SM (R14-proven) + register diet.
__global__ void __launch_bounds__(256, 5) fused_attn_copy(
    const float* __restrict__ kv, const int* __restrict__ ctx_len,
    float* __restrict__ out)
{
    int blk   = blockIdx.x;
    int chunk = blk & (NCHUNK - 1);
    int h     = (blk >> 5) & (NKVH - 1);
    int b     = blk >> 6;
    int warp  = threadIdx.x >> 5, lane = threadIdx.x & 31;
    int half  = lane >> 4, li = lane & 15;
    int pos   = ctx_len[b];

    size_t kb = (((size_t)b * 2 + 0) * NKVH + h) * (size_t)(MAXS * HD);
    const float4* kvbase = (const float4*)(kv + kb);               // k plane; v at +DV
    float4*       obase  = (float4*)(out + NB * HIDDEN + kb);      // k plane; v at +DV

    int hq = h * 2;
    int d4 = li * 4;
    float4 q0 = *(const float4*)&g_q[((size_t)b * NQH + hq)     * HD + d4];
    float4 q1 = *(const float4*)&g_q[((size_t)b * NQH + hq + 1) * HD + d4];
    const float scale = 0.125f;   // 64^-0.5, folded into q
    q0.x *= scale; q0.y *= scale; q0.z *= scale; q0.w *= scale;
    q1.x *= scale; q1.y *= scale; q1.z *= scale; q1.w *= scale;

    float m0 = -1e30f, l0 = 0.f, m1 = -1e30f, l1 = 0.f;
    float4 a0 = make_float4(0.f, 0.f, 0.f, 0.f);
    float4 a1 = make_float4(0.f, 0.f, 0.f, 0.f);

    int row0 = chunk * CHUNK + warp * (CHUNK / 8);
#pragma unroll 8
    for (int i = 0; i < CHUNK / 16; i++) {          // 2 rows per iter
        int m = row0 + 2 * i + half;                // per-half row
        size_t o4 = (size_t)m * (HD / 4) + li;
        float4 kd, vd;
        if (m == pos) {                             // rare: new-token row
            kd = *(const float4*)&g_k[((size_t)b * NKVH + h) * HD + d4];
            vd = *(const float4*)&g_v[((size_t)b * NKVH + h) * HD + d4];
        } else {
            kd = __ldcs(kvbase + o4);
            vd = __ldcs(kvbase + DV + o4);
        }
        __stcs(obase + o4, kd);
        __stcs(obase + DV + o4, vd);

        if (row0 + 2 * i <= pos) {                  // warp-uniform guard
            float p0 = kd.x * q0.x + kd.y * q0.y + kd.z * q0.z + kd.w * q0.w;
            float p1 = kd.x * q1.x + kd.y * q1.y + kd.z * q1.z + kd.w * q1.w;
#pragma unroll
            for (int sft = 8; sft > 0; sft >>= 1) { // stays within 16-lane half
                p0 += __shfl_xor_sync(0xffffffffu, p0, sft);
                p1 += __shfl_xor_sync(0xffffffffu, p1, sft);
            }
            if (m <= pos) {                          // per-half, ALU only
                float nm0 = fmaxf(m0, p0), nm1 = fmaxf(m1, p1);
                float f0 = __expf(m0 - nm0), w0 = __expf(p0 - nm0);
                float f1 = __expf(m1 - nm1), w1 = __expf(p1 - nm1);
                l0 = l0 * f0 + w0;  l1 = l1 * f1 + w1;
                a0.x = a0.x * f0 + w0 * vd.x;  a0.y = a0.y * f0 + w0 * vd.y;
                a0.z = a0.z * f0 + w0 * vd.z;  a0.w = a0.w * f0 + w0 * vd.w;
                a1.x = a1.x * f1 + w1 * vd.x;  a1.y = a1.y * f1 + w1 * vd.y;
                a1.z = a1.z * f1 + w1 * vd.z;  a1.w = a1.w * f1 + w1 * vd.w;
                m0 = nm0; m1 = nm1;
            }
        }
    }

    // merge the two half-warp softmax streams per head (shfl_xor 16)
    {
        float mo = __shfl_xor_sync(0xffffffffu, m0, 16);
        float lo = __shfl_xor_sync(0xffffffffu, l0, 16);
        float4 ao;
        ao.x = __shfl_xor_sync(0xffffffffu, a0.x, 16);
        ao.y = __shfl_xor_sync(0xffffffffu, a0.y, 16);
        ao.z = __shfl_xor_sync(0xffffffffu, a0.z, 16);
        ao.w = __shfl_xor_sync(0xffffffffu, a0.w, 16);
        float M = fmaxf(m0, mo);
        float e0 = __expf(m0 - M), e1 = __expf(mo - M);
        l0 = l0 * e0 + lo * e1;
        a0.x = a0.x * e0 + ao.x * e1;  a0.y = a0.y * e0 + ao.y * e1;
        a0.z = a0.z * e0 + ao.z * e1;  a0.w = a0.w * e0 + ao.w * e1;
        m0 = M;
    }
    {
        float mo = __shfl_xor_sync(0xffffffffu, m1, 16);
        float lo = __shfl_xor_sync(0xffffffffu, l1, 16);
        float4 ao;
        ao.x = __shfl_xor_sync(0xffffffffu, a1.x, 16);
        ao.y = __shfl_xor_sync(0xffffffffu, a1.y, 16);
        ao.z = __shfl_xor_sync(0xffffffffu, a1.z, 16);
        ao.w = __shfl_xor_sync(0xffffffffu, a1.w, 16);
        float M = fmaxf(m1, mo);
        float e0 = __expf(m1 - M), e1 = __expf(mo - M);
        l1 = l1 * e0 + lo * e1;
        a1.x = a1.x * e0 + ao.x * e1;  a1.y = a1.y * e0 + ao.y * e1;
        a1.z = a1.z * e0 + ao.z * e1;  a1.w = a1.w * e0 + ao.w * e1;
        m1 = M;
    }

    // cross-warp combine
    __shared__ float sm[2][8], sl[2][8], sa[2][8][HD];
    if (lane == 0) { sm[0][warp] = m0; sl[0][warp] = l0; sm[1][warp] = m1; sl[1][warp] = l1; }
    if (half == 0) {
        *(float4*)&sa[0][warp][d4] = a0;
        *(float4*)&sa[1][warp][d4] = a1;
    }
    __syncthreads();

    int t = threadIdx.x;
    if (t < 128) {
        int g = t >> 6, d = t & 63;
        float M = -1e30f;
#pragma unroll
        for (int w = 0; w < 8; w++) M = fmaxf(M, sm[g][w]);
        float L = 0.f, A = 0.f;
#pragma unroll
        for (int w = 0; w < 8; w++) {
            float e = __expf(sm[g][w] - M);
            L += sl[g][w] * e;
            A += sa[g][w][d] * e;
        }
        int head = (b * NKVH + h) * 2 + g;
        int pi = head * NCHUNK + chunk;
        if (d == 0) { g_pm[pi] = M; g_pl[pi] = L; }
        g_pa[(size_t)pi * HD + d] = A;
    }
}

// ---------------- kernel 3: combine + output projection ---------------------
// grid 256: blk -> b = blk>>3, eblk = blk&7. 256 threads. (R13 exact)
__global__ void __launch_bounds__(256) outproj_kernel(
    const float* __restrict__ out_w, float* __restrict__ out)
{
    int blk = blockIdx.x;
    int b = blk >> 3, eblk = blk & 7;
    int t = threadIdx.x;
    int w = t >> 5, lane = t & 31;
    __shared__ float se[NQH][NCHUNK];
    __shared__ float sinvL[NQH];
    __shared__ float sc[HIDDEN];

    // phase 1a: one warp per head; lane c handles chunk c (NCHUNK == 32)
    if (w < NQH) {
        int head = b * NQH + w;
        float pm = g_pm[head * NCHUNK + lane];
        float pl = g_pl[head * NCHUNK + lane];
        float M = pm;
#pragma unroll
        for (int s = 16; s > 0; s >>= 1)
            M = fmaxf(M, __shfl_xor_sync(0xffffffffu, M, s));
        float e = __expf(pm - M);
        float lp = pl * e;
#pragma unroll
        for (int s = 16; s > 0; s >>= 1)
            lp += __shfl_xor_sync(0xffffffffu, lp, s);
        se[w][lane] = e;
        if (lane == 0) sinvL[w] = 1.f / lp;
    }
    __syncthreads();

    // phase 1b: thread t -> head g, dim d; 32 independent loads, pure FMA
    {
        int g = t >> 6, d = t & 63;
        int head = b * NQH + g;
        const float* pa = g_pa + (size_t)head * NCHUNK * HD + d;
        float A = 0.f;
#pragma unroll
        for (int c = 0; c < NCHUNK; c++)
            A += pa[(size_t)c * HD] * se[g][c];
        sc[t] = A * sinvL[g];
    }
    __syncthreads();

    // phase 2: warp w -> outputs e = eblk*32 + w*4 + j, j=0..3
    int e0 = eblk * 32 + w * 4;
    const float4* c4 = (const float4*)sc + lane * 2;
    float4 ca = c4[0], cb = c4[1];
    float s[4];
#pragma unroll
    for (int j = 0; j < 4; j++) {
        const float4* w4p = (const float4*)(out_w + (size_t)(e0 + j) * HIDDEN) + lane * 2;
        s[j] = dot4(w4p[0], ca) + dot4(w4p[1], cb);
    }
#pragma unroll
    for (int sft = 16; sft > 0; sft >>= 1) {
#pragma unroll
        for (int j = 0; j < 4; j++)
            s[j] += __shfl_xor_sync(0xffffffffu, s[j], sft);
    }
    if (lane == 0) {
#pragma unroll
        for (int j = 0; j < 4; j++)
            out[b * HIDDEN + e0 + j] = s[j];
    }
}

// ---------------- launch ----------------------------------------------------
extern "C" void kernel_launch(void* const* d_in, const int* in_sizes, int n_in,
                              void* d_out, int out_size)
{
    const float* x     = (const float*)d_in[0];
    const float* kv    = (const float*)d_in[1];
    const int*   ctx   = (const int*)d_in[2];
    const float* rope  = (const float*)d_in[3];
    const float* qkv_w = (const float*)d_in[4];
    const float* qkv_b = (const float*)d_in[5];
    const float* out_w = (const float*)d_in[6];
    float* out = (float*)d_out;

    qkv_rope_kernel<<<1024, 256>>>(x, ctx, rope, qkv_w, qkv_b);
    fused_attn_copy<<<NB * NKVH * NCHUNK, 256>>>(kv, ctx, out);
    outproj_kernel<<<256, 256>>>(out_w, out);
}

// round 17
// speedup vs baseline: 1.0997x; 1.0997x over previous
#include <cuda_runtime.h>

#define NB 32
#define HIDDEN 256
#define NQH 4
#define NKVH 2
#define HD 64
#define QKV_DIM 512
#define MAXS 8192
#define CHUNK 256
#define NCHUNK (MAXS / CHUNK)          // 32 == warp size (outproj phase-1 relies on this)
#define NHEAD (NB * NQH)               // 128

// ---------------- scratch (device globals) ----------------------------------
__device__ float g_q[NB * HIDDEN];
__device__ float g_k[NB * NKVH * HD];
__device__ float g_v[NB * NKVH * HD];
__device__ float g_pm[NHEAD * NCHUNK];
__device__ float g_pl[NHEAD * NCHUNK];
__device__ float g_pa[NHEAD * NCHUNK * HD];

__device__ __forceinline__ float dot4(float4 a, float4 b) {
    return a.x * b.x + a.y * b.y + a.z * b.z + a.w * b.w;
}

// ---------------- kernel 1: qkv projection + rope, warp-per-rope-pair -------
// (R7/R9 exact: 8192 warps, chain depth 1, measured ~6.2us)
__global__ void __launch_bounds__(256) qkv_rope_kernel(
    const float* __restrict__ x, const int* __restrict__ ctx_len,
    const float* __restrict__ rope, const float* __restrict__ qkv_w,
    const float* __restrict__ qkv_b)
{
    int W    = blockIdx.x * 8 + (threadIdx.x >> 5);
    int lane = threadIdx.x & 31;
    int b    = W & 31;
    int d    = (W >> 5) & 31;
    int hid  = W >> 10;                   // 0..7
    int elo  = hid * HD + d;
    int ehi  = elo + 32;

    const float4* wlo = (const float4*)(qkv_w + (size_t)elo * HIDDEN) + lane * 2;
    const float4* whi = (const float4*)(qkv_w + (size_t)ehi * HIDDEN) + lane * 2;
    const float4* xb  = (const float4*)(x + (size_t)b * HIDDEN) + lane * 2;

    float4 wl0 = wlo[0], wl1 = wlo[1];
    float4 wh0 = whi[0], wh1 = whi[1];
    float4 x0  = xb[0],  x1  = xb[1];

    float slo = dot4(wl0, x0) + dot4(wl1, x1);
    float shi = dot4(wh0, x0) + dot4(wh1, x1);
#pragma unroll
    for (int s = 16; s > 0; s >>= 1) {
        slo += __shfl_xor_sync(0xffffffffu, slo, s);
        shi += __shfl_xor_sync(0xffffffffu, shi, s);
    }

    if (lane == 0) {
        slo += qkv_b[elo];
        shi += qkv_b[ehi];
        float vlo, vhi;
        if (hid < NQH + NKVH) {           // q or k: rope
            int pos = ctx_len[b];
            float c = rope[(size_t)pos * HD + d];
            float s = rope[(size_t)pos * HD + 32 + d];
            vlo = slo * c - shi * s;
            vhi = slo * s + shi * c;
        } else {
            vlo = slo; vhi = shi;
        }
        if (hid < NQH) {
            g_q[b * HIDDEN + hid * HD + d]      = vlo;
            g_q[b * HIDDEN + hid * HD + d + 32] = vhi;
        } else if (hid < NQH + NKVH) {
            int hk = hid - NQH;
            g_k[(b * NKVH + hk) * HD + d]      = vlo;
            g_k[(b * NKVH + hk) * HD + d + 32] = vhi;
        } else {
            int hv = hid - NQH - NKVH;
            g_v[(b * NKVH + hv) * HD + d]      = vlo;
            g_v[(b * NKVH + hv) * HD + d + 32] = vhi;
        }
    }
}

// ---------------- kernel 2: fused KV-cache copy + flash-decode partials -----
// 2048 CTAs x 256 threads; reg-capped for 5 CTAs/SM. kn/vn loaded lazily.
// (R14 exact — measured 95.0us)
__global__ void __launch_bounds__(256, 5) fused_attn_copy(
    const float* __restrict__ kv, const int* __restrict__ ctx_len,
    float* __restrict__ out)
{
    int blk   = blockIdx.x;
    int chunk = blk & (NCHUNK - 1);
    int h     = (blk >> 5) & (NKVH - 1);
    int b     = blk >> 6;
    int warp  = threadIdx.x >> 5, lane = threadIdx.x & 31;
    int half  = lane >> 4, li = lane & 15;
    int pos   = ctx_len[b];

    size_t kb = (((size_t)b * 2 + 0) * NKVH + h) * (size_t)(MAXS * HD);
    size_t vb = kb + (size_t)NKVH * MAXS * HD;
    const float4* kp4 = (const float4*)(kv + kb);
    const float4* vp4 = (const float4*)(kv + vb);
    float4* okp4 = (float4*)(out + NB * HIDDEN + kb);
    float4* ovp4 = (float4*)(out + NB * HIDDEN + vb);

    int hq = h * 2;
    int d4 = li * 4;
    float4 q0 = *(const float4*)&g_q[((size_t)b * NQH + hq)     * HD + d4];
    float4 q1 = *(const float4*)&g_q[((size_t)b * NQH + hq + 1) * HD + d4];

    float m0 = -1e30f, l0 = 0.f, m1 = -1e30f, l1 = 0.f;
    float4 a0 = make_float4(0.f, 0.f, 0.f, 0.f);
    float4 a1 = make_float4(0.f, 0.f, 0.f, 0.f);
    const float scale = 0.125f;   // 64^-0.5

    int row0 = chunk * CHUNK + warp * (CHUNK / 8);
#pragma unroll 8
    for (int i = 0; i < CHUNK / 16; i++) {          // 2 rows per iter
        int m = row0 + 2 * i + half;                // per-half row
        size_t o4 = (size_t)m * (HD / 4) + li;
        float4 kd, vd;
        if (m == pos) {                             // rare: new-token row
            kd = *(const float4*)&g_k[((size_t)b * NKVH + h) * HD + d4];
            vd = *(const float4*)&g_v[((size_t)b * NKVH + h) * HD + d4];
        } else {
            kd = __ldcs(kp4 + o4);
            vd = __ldcs(vp4 + o4);
        }
        __stcs(okp4 + o4, kd);
        __stcs(ovp4 + o4, vd);

        if (row0 + 2 * i <= pos) {                  // warp-uniform guard
            float p0 = kd.x * q0.x + kd.y * q0.y + kd.z * q0.z + kd.w * q0.w;
            float p1 = kd.x * q1.x + kd.y * q1.y + kd.z * q1.z + kd.w * q1.w;
#pragma unroll
            for (int sft = 8; sft > 0; sft >>= 1) { // stays within 16-lane half
                p0 += __shfl_xor_sync(0xffffffffu, p0, sft);
                p1 += __shfl_xor_sync(0xffffffffu, p1, sft);
            }
            if (m <= pos) {                          // per-half, ALU only
                p0 *= scale; p1 *= scale;
                float nm0 = fmaxf(m0, p0), nm1 = fmaxf(m1, p1);
                float f0 = __expf(m0 - nm0), w0 = __expf(p0 - nm0);
                float f1 = __expf(m1 - nm1), w1 = __expf(p1 - nm1);
                l0 = l0 * f0 + w0;  l1 = l1 * f1 + w1;
                a0.x = a0.x * f0 + w0 * vd.x;  a0.y = a0.y * f0 + w0 * vd.y;
                a0.z = a0.z * f0 + w0 * vd.z;  a0.w = a0.w * f0 + w0 * vd.w;
                a1.x = a1.x * f1 + w1 * vd.x;  a1.y = a1.y * f1 + w1 * vd.y;
                a1.z = a1.z * f1 + w1 * vd.z;  a1.w = a1.w * f1 + w1 * vd.w;
                m0 = nm0; m1 = nm1;
            }
        }
    }

    // merge the two half-warp softmax streams per head (shfl_xor 16)
    {
        float mo = __shfl_xor_sync(0xffffffffu, m0, 16);
        float lo = __shfl_xor_sync(0xffffffffu, l0, 16);
        float4 ao;
        ao.x = __shfl_xor_sync(0xffffffffu, a0.x, 16);
        ao.y = __shfl_xor_sync(0xffffffffu, a0.y, 16);
        ao.z = __shfl_xor_sync(0xffffffffu, a0.z, 16);
        ao.w = __shfl_xor_sync(0xffffffffu, a0.w, 16);
        float M = fmaxf(m0, mo);
        float e0 = __expf(m0 - M), e1 = __expf(mo - M);
        l0 = l0 * e0 + lo * e1;
        a0.x = a0.x * e0 + ao.x * e1;  a0.y = a0.y * e0 + ao.y * e1;
        a0.z = a0.z * e0 + ao.z * e1;  a0.w = a0.w * e0 + ao.w * e1;
        m0 = M;
    }
    {
        float mo = __shfl_xor_sync(0xffffffffu, m1, 16);
        float lo = __shfl_xor_sync(0xffffffffu, l1, 16);
        float4 ao;
        ao.x = __shfl_xor_sync(0xffffffffu, a1.x, 16);
        ao.y = __shfl_xor_sync(0xffffffffu, a1.y, 16);
        ao.z = __shfl_xor_sync(0xffffffffu, a1.z, 16);
        ao.w = __shfl_xor_sync(0xffffffffu, a1.w, 16);
        float M = fmaxf(m1, mo);
        float e0 = __expf(m1 - M), e1 = __expf(mo - M);
        l1 = l1 * e0 + lo * e1;
        a1.x = a1.x * e0 + ao.x * e1;  a1.y = a1.y * e0 + ao.y * e1;
        a1.z = a1.z * e0 + ao.z * e1;  a1.w = a1.w * e0 + ao.w * e1;
        m1 = M;
    }

    // cross-warp combine
    __shared__ float sm[2][8], sl[2][8], sa[2][8][HD];
    if (lane == 0) { sm[0][warp] = m0; sl[0][warp] = l0; sm[1][warp] = m1; sl[1][warp] = l1; }
    if (half == 0) {
        *(float4*)&sa[0][warp][d4] = a0;
        *(float4*)&sa[1][warp][d4] = a1;
    }
    __syncthreads();

    int t = threadIdx.x;
    if (t < 128) {
        int g = t >> 6, d = t & 63;
        float M = -1e30f;
#pragma unroll
        for (int w = 0; w < 8; w++) M = fmaxf(M, sm[g][w]);
        float L = 0.f, A = 0.f;
#pragma unroll
        for (int w = 0; w < 8; w++) {
            float e = __expf(sm[g][w] - M);
            L += sl[g][w] * e;
            A += sa[g][w][d] * e;
        }
        int head = (b * NKVH + h) * 2 + g;
        int pi = head * NCHUNK + chunk;
        if (d == 0) { g_pm[pi] = M; g_pl[pi] = L; }
        g_pa[(size_t)pi * HD + d] = A;
    }
}

// ---------------- kernel 3: combine + output projection ---------------------
// grid 256: blk -> b = blk>>3, eblk = blk&7. 256 threads. (R13 exact)
__global__ void __launch_bounds__(256) outproj_kernel(
    const float* __restrict__ out_w, float* __restrict__ out)
{
    int blk = blockIdx.x;
    int b = blk >> 3, eblk = blk & 7;
    int t = threadIdx.x;
    int w = t >> 5, lane = t & 31;
    __shared__ float se[NQH][NCHUNK];
    __shared__ float sinvL[NQH];
    __shared__ float sc[HIDDEN];

    // phase 1a: one warp per head; lane c handles chunk c (NCHUNK == 32)
    if (w < NQH) {
        int head = b * NQH + w;
        float pm = g_pm[head * NCHUNK + lane];
        float pl = g_pl[head * NCHUNK + lane];
        float M = pm;
#pragma unroll
        for (int s = 16; s > 0; s >>= 1)
            M = fmaxf(M, __shfl_xor_sync(0xffffffffu, M, s));
        float e = __expf(pm - M);
        float lp = pl * e;
#pragma unroll
        for (int s = 16; s > 0; s >>= 1)
            lp += __shfl_xor_sync(0xffffffffu, lp, s);
        se[w][lane] = e;
        if (lane == 0) sinvL[w] = 1.f / lp;
    }
    __syncthreads();

    // phase 1b: thread t -> head g, dim d; 32 independent loads, pure FMA
    {
        int g = t >> 6, d = t & 63;
        int head = b * NQH + g;
        const float* pa = g_pa + (size_t)head * NCHUNK * HD + d;
        float A = 0.f;
#pragma unroll
        for (int c = 0; c < NCHUNK; c++)
            A += pa[(size_t)c * HD] * se[g][c];
        sc[t] = A * sinvL[g];
    }
    __syncthreads();

    // phase 2: warp w -> outputs e = eblk*32 + w*4 + j, j=0..3
    int e0 = eblk * 32 + w * 4;
    const float4* c4 = (const float4*)sc + lane * 2;
    float4 ca = c4[0], cb = c4[1];
    float s[4];
#pragma unroll
    for (int j = 0; j < 4; j++) {
        const float4* w4p = (const float4*)(out_w + (size_t)(e0 + j) * HIDDEN) + lane * 2;
        s[j] = dot4(w4p[0], ca) + dot4(w4p[1], cb);
    }
#pragma unroll
    for (int sft = 16; sft > 0; sft >>= 1) {
#pragma unroll
        for (int j = 0; j < 4; j++)
            s[j] += __shfl_xor_sync(0xffffffffu, s[j], sft);
    }
    if (lane == 0) {
#pragma unroll
        for (int j = 0; j < 4; j++)
            out[b * HIDDEN + e0 + j] = s[j];
    }
}

// ---------------- launch ----------------------------------------------------
extern "C" void kernel_launch(void* const* d_in, const int* in_sizes, int n_in,
                              void* d_out, int out_size)
{
    const float* x     = (const float*)d_in[0];
    const float* kv    = (const float*)d_in[1];
    const int*   ctx   = (const int*)d_in[2];
    const float* rope  = (const float*)d_in[3];
    const float* qkv_w = (const float*)d_in[4];
    const float* qkv_b = (const float*)d_in[5];
    const float* out_w = (const float*)d_in[6];
    float* out = (float*)d_out;

    qkv_rope_kernel<<<1024, 256>>>(x, ctx, rope, qkv_w, qkv_b);
    fused_attn_copy<<<NB * NKVH * NCHUNK, 256>>>(kv, ctx, out);
    outproj_kernel<<<256, 256>>>(out_w, out);
}